// round 2
// baseline (speedup 1.0000x reference)
#include <cuda_runtime.h>
#include <cstdint>

#define Hdim 768
#define Nn   50
#define Bb   1024

// ---------------- scratch (static device globals; no allocation) ----------------
__device__ float g_drep[Bb * Hdim];
__device__ float g_wvec[Bb * Hdim];
__device__ float g_R[Bb * Hdim];
__device__ float g_G[Bb * Hdim];

// ---------------- kernel 1: per-batch reductions over n ----------------
// d_rep[b,h] = mean_n sv[b,n,h];  w[b,h] = sum_n q_w[n]*mask[b,n]*sv[b,n,h]
__global__ void k1_reduce(const float* __restrict__ sv,
                          const int* __restrict__ mask,
                          const float* __restrict__ qw) {
    const int b = blockIdx.x;
    const int h = threadIdx.x;  // 768 threads
    __shared__ float sq[Nn];
    if (h < Nn) sq[h] = qw[h] * (mask[b * Nn + h] != 0 ? 1.0f : 0.0f);
    __syncthreads();

    const float* base = sv + (size_t)b * Nn * Hdim + h;
    float ad = 0.0f, aw = 0.0f;
#pragma unroll
    for (int n = 0; n < Nn; n++) {
        float v = base[(size_t)n * Hdim];
        ad += v;
        aw = fmaf(sq[n], v, aw);
    }
    g_drep[b * Hdim + h] = ad * (1.0f / (float)Nn);
    g_wvec[b * Hdim + h] = aw;
}

// ---------------- kernel 2: tf32 tensor-core GEMM (NT) ----------------
// z=0: R = d_rep @ W_rel^T   z=1: G = w @ W_sim^T
// C[m,n] = sum_k A[m,k]*B[n,k], M=1024, N=768, K=768
#define BM 64
#define BN 64
#define BK 32
#define KPAD 36

__device__ __forceinline__ uint32_t f2tf32(float x) {
    uint32_t r;
    asm("cvt.rna.tf32.f32 %0, %1;" : "=r"(r) : "f"(x));
    return r;
}

__device__ __forceinline__ void mma_tf32(float d[4], const uint32_t a[4], const uint32_t b[2]) {
    asm volatile(
        "mma.sync.aligned.m16n8k8.row.col.f32.tf32.tf32.f32 "
        "{%0,%1,%2,%3}, {%4,%5,%6,%7}, {%8,%9}, {%0,%1,%2,%3};"
        : "+f"(d[0]), "+f"(d[1]), "+f"(d[2]), "+f"(d[3])
        : "r"(a[0]), "r"(a[1]), "r"(a[2]), "r"(a[3]), "r"(b[0]), "r"(b[1]));
}

__global__ void k2_gemm(const float* __restrict__ Wrel, const float* __restrict__ Wsim) {
    const int z = blockIdx.z;
    const float* A  = z ? g_wvec : g_drep;
    const float* Bm = z ? Wsim   : Wrel;
    float*       C  = z ? g_G    : g_R;

    const int m0 = blockIdx.y * BM;
    const int n0 = blockIdx.x * BN;

    __shared__ uint32_t As[BM * KPAD];
    __shared__ uint32_t Bs[BN * KPAD];

    const int tid  = threadIdx.x;     // 128
    const int lane = tid & 31;
    const int wid  = tid >> 5;        // 4 warps, 2x2
    const int wm   = wid >> 1;
    const int wn   = wid & 1;
    const int grp  = lane >> 2;
    const int tg   = lane & 3;

    float acc[2][4][4];
#pragma unroll
    for (int mi = 0; mi < 2; mi++)
#pragma unroll
        for (int ni = 0; ni < 4; ni++)
#pragma unroll
            for (int r = 0; r < 4; r++) acc[mi][ni][r] = 0.0f;

    for (int kt = 0; kt < Hdim / BK; kt++) {
        const int k0 = kt * BK;
#pragma unroll
        for (int p = 0; p < 4; p++) {
            int r  = (tid >> 3) + p * 16;
            int c4 = (tid & 7);
            float4 va = *(const float4*)&A[(size_t)(m0 + r) * Hdim + k0 + c4 * 4];
            uint4 ta = {f2tf32(va.x), f2tf32(va.y), f2tf32(va.z), f2tf32(va.w)};
            *(uint4*)&As[r * KPAD + c4 * 4] = ta;
            float4 vb = *(const float4*)&Bm[(size_t)(n0 + r) * Hdim + k0 + c4 * 4];
            uint4 tb = {f2tf32(vb.x), f2tf32(vb.y), f2tf32(vb.z), f2tf32(vb.w)};
            *(uint4*)&Bs[r * KPAD + c4 * 4] = tb;
        }
        __syncthreads();

#pragma unroll
        for (int kk = 0; kk < 4; kk++) {
            const int c0 = kk * 8 + tg;
            uint32_t afr[2][4];
#pragma unroll
            for (int mi = 0; mi < 2; mi++) {
                int r0 = wm * 32 + mi * 16 + grp;
                afr[mi][0] = As[r0 * KPAD + c0];
                afr[mi][1] = As[(r0 + 8) * KPAD + c0];
                afr[mi][2] = As[r0 * KPAD + c0 + 4];
                afr[mi][3] = As[(r0 + 8) * KPAD + c0 + 4];
            }
            uint32_t bfr[4][2];
#pragma unroll
            for (int ni = 0; ni < 4; ni++) {
                int nr = wn * 32 + ni * 8 + grp;
                bfr[ni][0] = Bs[nr * KPAD + kk * 8 + tg];
                bfr[ni][1] = Bs[nr * KPAD + kk * 8 + tg + 4];
            }
#pragma unroll
            for (int mi = 0; mi < 2; mi++)
#pragma unroll
                for (int ni = 0; ni < 4; ni++) mma_tf32(acc[mi][ni], afr[mi], bfr[ni]);
        }
        __syncthreads();
    }

#pragma unroll
    for (int mi = 0; mi < 2; mi++) {
#pragma unroll
        for (int ni = 0; ni < 4; ni++) {
            int row = m0 + wm * 32 + mi * 16 + grp;
            int col = n0 + wn * 32 + ni * 8 + tg * 2;
            C[(size_t)row * Hdim + col]           = acc[mi][ni][0];
            C[(size_t)row * Hdim + col + 1]       = acc[mi][ni][1];
            C[(size_t)(row + 8) * Hdim + col]     = acc[mi][ni][2];
            C[(size_t)(row + 8) * Hdim + col + 1] = acc[mi][ni][3];
        }
    }
}

// ---------------- kernel 3: per-(b,n) dots + closed-form epilogue ----------------
__device__ __forceinline__ float wsum(float v) {
    v += __shfl_xor_sync(0xffffffffu, v, 16);
    v += __shfl_xor_sync(0xffffffffu, v, 8);
    v += __shfl_xor_sync(0xffffffffu, v, 4);
    v += __shfl_xor_sync(0xffffffffu, v, 2);
    v += __shfl_xor_sync(0xffffffffu, v, 1);
    return v;
}

__global__ void k3_final(const float* __restrict__ sv,
                         const int* __restrict__ mask,
                         const float* __restrict__ Wc,
                         const float* __restrict__ bmat,
                         const float* __restrict__ qw,
                         const float* __restrict__ qb,
                         float* __restrict__ out) {
    const int b    = blockIdx.x;
    const int tid  = threadIdx.x;  // 256
    const int lane = tid & 31;
    const int wid  = tid >> 5;

    __shared__ float4 sr4[Hdim / 4], sg4[Hdim / 4], sc4[Hdim / 4];
    __shared__ float sCont[64], sRel[64], sSim[64], sM[64], sQw[64];

    for (int i = tid; i < Hdim / 4; i += 256) {
        sr4[i] = ((const float4*)(g_R + (size_t)b * Hdim))[i];
        sg4[i] = ((const float4*)(g_G + (size_t)b * Hdim))[i];
        sc4[i] = ((const float4*)Wc)[i];
    }
    if (tid < 64) {
        sM[tid]  = (tid < Nn && mask[b * Nn + tid] != 0) ? 1.0f : 0.0f;
        sQw[tid] = (tid < Nn) ? qw[tid] : 0.0f;
        sCont[tid] = 0.0f; sRel[tid] = 0.0f; sSim[tid] = 0.0f;
    }
    __syncthreads();

    // each warp: full-768 dot (against W_cont, R[b], G[b]) for its n's
    for (int n = wid; n < Nn; n += 8) {
        const float4* row = (const float4*)(sv + ((size_t)b * Nn + n) * Hdim);
        float dc = 0.0f, dr = 0.0f, dg = 0.0f;
#pragma unroll
        for (int i = 0; i < 6; i++) {
            int idx = lane + i * 32;
            float4 v = row[idx];
            float4 a = sc4[idx];
            float4 r = sr4[idx];
            float4 g = sg4[idx];
            dc = fmaf(v.x, a.x, dc); dc = fmaf(v.y, a.y, dc);
            dc = fmaf(v.z, a.z, dc); dc = fmaf(v.w, a.w, dc);
            dr = fmaf(v.x, r.x, dr); dr = fmaf(v.y, r.y, dr);
            dr = fmaf(v.z, r.z, dr); dr = fmaf(v.w, r.w, dr);
            dg = fmaf(v.x, g.x, dg); dg = fmaf(v.y, g.y, dg);
            dg = fmaf(v.z, g.z, dg); dg = fmaf(v.w, g.w, dg);
        }
        dc = wsum(dc); dr = wsum(dr); dg = wsum(dg);
        if (lane == 0) { sCont[n] = dc; sRel[n] = dr; sSim[n] = dg; }
    }
    __syncthreads();

    if (wid == 0) {
        const float b00 = bmat[0];
        const float qbv = qb[0];
        const float m1 = sM[lane],       m2 = sM[lane + 32];
        const float q1 = sQw[lane],      q2 = sQw[lane + 32];
        const bool  v2 = (lane + 32) < Nn;

        const float Qm = wsum(m1 * q1 + m2 * q2);        // sum_m q_w[m]*mask[m]
        const float sn = wsum(m1 + m2);                  // sent_num

        // s[n] = q_b + mask[n] * ((rel + cont + b00)*Qm + simdot)
        float s1 = qbv + m1 * ((sRel[lane] + sCont[lane] + b00) * Qm + sSim[lane]);
        float s2 = v2 ? (qbv + m2 * ((sRel[lane + 32] + sCont[lane + 32] + b00) * Qm + sSim[lane + 32]))
                      : 0.0f;

        // layernorm over the 50 sentences
        const float mu = wsum(s1 + (v2 ? s2 : 0.0f)) * (1.0f / (float)Nn);
        const float d1 = s1 - mu;
        const float d2 = v2 ? (s2 - mu) : 0.0f;
        const float var = wsum(d1 * d1 + d2 * d2) * (1.0f / (float)Nn);
        const float rstd = rsqrtf(var + 1e-6f);

        const float sig1 = 1.0f / (1.0f + expf(-d1 * rstd));
        const float sig2 = 1.0f / (1.0f + expf(-d2 * rstd));

        // rank-1 closed form:  M = p * mask^T,  x*sn = (1-l) + l*p[n]*sn
        const float S = wsum(sig1 * m1 + sig2 * m2);
        const float inv = 1.0f / S;
        const float p1 = sig1 * m1 * inv;
        const float p2 = sig2 * m2 * inv;

        float o1 = (1.0f / (1.0f + expf(-(0.2f + 0.8f * p1 * sn)))) * m1;
        out[b * Nn + lane] = o1;
        if (v2) {
            float o2 = (1.0f / (1.0f + expf(-(0.2f + 0.8f * p2 * sn)))) * m2;
            out[b * Nn + lane + 32] = o2;
        }
    }
}

// ---------------- launch ----------------
extern "C" void kernel_launch(void* const* d_in, const int* in_sizes, int n_in,
                              void* d_out, int out_size) {
    const float* sv   = (const float*)d_in[0];
    const int*   mask = (const int*)d_in[1];
    const float* Wc   = (const float*)d_in[2];
    const float* Wsim = (const float*)d_in[3];
    const float* Wrel = (const float*)d_in[4];
    const float* bmat = (const float*)d_in[5];
    const float* qw   = (const float*)d_in[6];
    const float* qb   = (const float*)d_in[7];
    float*       out  = (float*)d_out;

    k1_reduce<<<Bb, Hdim>>>(sv, mask, qw);
    k2_gemm<<<dim3(Hdim / BN, Bb / BM, 2), 128>>>(Wrel, Wsim);
    k3_final<<<Bb, 256>>>(sv, mask, Wc, bmat, qw, qb, out);
}

// round 3
// speedup vs baseline: 1.5269x; 1.5269x over previous
#include <cuda_runtime.h>
#include <cstdint>

#define Hdim 768
#define Nn   50
#define Bb   1024

// ---------------- scratch (static device globals; no allocation) ----------------
__device__ float g_drep[Bb * Hdim];
__device__ float g_wvec[Bb * Hdim];
__device__ float g_R[Bb * Hdim];
__device__ float g_G[Bb * Hdim];

// ---------------- kernel 1: per-batch reductions over n (float4) ----------------
// d_rep[b,h] = mean_n sv[b,n,h];  w[b,h] = sum_n q_w[n]*mask[b,n]*sv[b,n,h]
__global__ __launch_bounds__(192) void k1_reduce(const float* __restrict__ sv,
                                                 const int* __restrict__ mask,
                                                 const float* __restrict__ qw) {
    const int b = blockIdx.x;
    const int t = threadIdx.x;  // 192 threads, one float4 column each (192*4 = 768)
    __shared__ float sq[Nn];
    if (t < Nn) sq[t] = qw[t] * (mask[b * Nn + t] != 0 ? 1.0f : 0.0f);
    __syncthreads();

    const float4* base = (const float4*)(sv + (size_t)b * Nn * Hdim) + t;
    float adx = 0.f, ady = 0.f, adz = 0.f, adw = 0.f;
    float awx = 0.f, awy = 0.f, awz = 0.f, aww = 0.f;
#pragma unroll 10
    for (int n = 0; n < Nn; n++) {
        float4 v = base[n * (Hdim / 4)];
        float s = sq[n];
        adx += v.x; ady += v.y; adz += v.z; adw += v.w;
        awx = fmaf(s, v.x, awx); awy = fmaf(s, v.y, awy);
        awz = fmaf(s, v.z, awz); aww = fmaf(s, v.w, aww);
    }
    const float inv = 1.0f / (float)Nn;
    float4 od = {adx * inv, ady * inv, adz * inv, adw * inv};
    float4 ow = {awx, awy, awz, aww};
    ((float4*)g_drep)[(size_t)b * (Hdim / 4) + t] = od;
    ((float4*)g_wvec)[(size_t)b * (Hdim / 4) + t] = ow;
}

// ---------------- kernel 2: tf32 tensor-core GEMM (NT), cp.async 2-stage ----------------
// z=0: R = d_rep @ W_rel^T   z=1: G = w @ W_sim^T
// C[m,n] = sum_k A[m,k]*B[n,k], M=1024, N=768, K=768
#define BM 64
#define BN 64
#define BK 32
#define KPAD 36
#define NKT (Hdim / BK)  // 24

__device__ __forceinline__ uint32_t f2tf32(float x) {
    uint32_t r;
    asm("cvt.rna.tf32.f32 %0, %1;" : "=r"(r) : "f"(x));
    return r;
}

__device__ __forceinline__ void cp_async16(void* smem_dst, const void* gmem_src) {
    uint32_t d = (uint32_t)__cvta_generic_to_shared(smem_dst);
    asm volatile("cp.async.cg.shared.global [%0], [%1], 16;" ::"r"(d), "l"(gmem_src));
}
__device__ __forceinline__ void cp_commit() { asm volatile("cp.async.commit_group;"); }
template <int N>
__device__ __forceinline__ void cp_wait() { asm volatile("cp.async.wait_group %0;" ::"n"(N)); }

__device__ __forceinline__ void mma_tf32(float d[4], const uint32_t a[4], const uint32_t b[2]) {
    asm volatile(
        "mma.sync.aligned.m16n8k8.row.col.f32.tf32.tf32.f32 "
        "{%0,%1,%2,%3}, {%4,%5,%6,%7}, {%8,%9}, {%0,%1,%2,%3};"
        : "+f"(d[0]), "+f"(d[1]), "+f"(d[2]), "+f"(d[3])
        : "r"(a[0]), "r"(a[1]), "r"(a[2]), "r"(a[3]), "r"(b[0]), "r"(b[1]));
}

__global__ __launch_bounds__(256) void k2_gemm(const float* __restrict__ Wrel,
                                               const float* __restrict__ Wsim) {
    const int z = blockIdx.z;
    const float* A  = z ? g_wvec : g_drep;
    const float* Bm = z ? Wsim   : Wrel;
    float*       C  = z ? g_G    : g_R;

    const int m0 = blockIdx.y * BM;
    const int n0 = blockIdx.x * BN;

    __shared__ float As[2][BM * KPAD];
    __shared__ float Bs[2][BN * KPAD];

    const int tid  = threadIdx.x;     // 256
    const int lane = tid & 31;
    const int wid  = tid >> 5;        // 8 warps: 2 (m) x 4 (n)
    const int wm   = wid >> 2;        // 0..1 -> 32 rows each
    const int wn   = wid & 3;         // 0..3 -> 16 cols each
    const int grp  = lane >> 2;
    const int tg   = lane & 3;

    // loader mapping: 512 float4 per operand tile, 256 threads -> 2 each
    const int lr  = tid >> 3;   // 0..31
    const int lc4 = tid & 7;    // 0..7

    float acc[2][2][4];
#pragma unroll
    for (int mi = 0; mi < 2; mi++)
#pragma unroll
        for (int ni = 0; ni < 2; ni++)
#pragma unroll
            for (int r = 0; r < 4; r++) acc[mi][ni][r] = 0.0f;

    // prefetch tile 0
    {
        const int k0 = 0;
#pragma unroll
        for (int p = 0; p < 2; p++) {
            int r = lr + p * 32;
            cp_async16(&As[0][r * KPAD + lc4 * 4], &A[(size_t)(m0 + r) * Hdim + k0 + lc4 * 4]);
            cp_async16(&Bs[0][r * KPAD + lc4 * 4], &Bm[(size_t)(n0 + r) * Hdim + k0 + lc4 * 4]);
        }
        cp_commit();
    }

    for (int kt = 0; kt < NKT; kt++) {
        const int st = kt & 1;
        if (kt + 1 < NKT) {
            const int k0 = (kt + 1) * BK;
            const int ns = (kt + 1) & 1;
#pragma unroll
            for (int p = 0; p < 2; p++) {
                int r = lr + p * 32;
                cp_async16(&As[ns][r * KPAD + lc4 * 4], &A[(size_t)(m0 + r) * Hdim + k0 + lc4 * 4]);
                cp_async16(&Bs[ns][r * KPAD + lc4 * 4], &Bm[(size_t)(n0 + r) * Hdim + k0 + lc4 * 4]);
            }
            cp_commit();
            cp_wait<1>();
        } else {
            cp_wait<0>();
        }
        __syncthreads();

#pragma unroll
        for (int kk = 0; kk < 4; kk++) {
            const int c0 = kk * 8 + tg;
            uint32_t afr[2][4];
#pragma unroll
            for (int mi = 0; mi < 2; mi++) {
                int r0 = wm * 32 + mi * 16 + grp;
                afr[mi][0] = f2tf32(As[st][r0 * KPAD + c0]);
                afr[mi][1] = f2tf32(As[st][(r0 + 8) * KPAD + c0]);
                afr[mi][2] = f2tf32(As[st][r0 * KPAD + c0 + 4]);
                afr[mi][3] = f2tf32(As[st][(r0 + 8) * KPAD + c0 + 4]);
            }
            uint32_t bfr[2][2];
#pragma unroll
            for (int ni = 0; ni < 2; ni++) {
                int nr = wn * 16 + ni * 8 + grp;
                bfr[ni][0] = f2tf32(Bs[st][nr * KPAD + c0]);
                bfr[ni][1] = f2tf32(Bs[st][nr * KPAD + c0 + 4]);
            }
#pragma unroll
            for (int mi = 0; mi < 2; mi++)
#pragma unroll
                for (int ni = 0; ni < 2; ni++) mma_tf32(acc[mi][ni], afr[mi], bfr[ni]);
        }
        __syncthreads();
    }

#pragma unroll
    for (int mi = 0; mi < 2; mi++) {
#pragma unroll
        for (int ni = 0; ni < 2; ni++) {
            int row = m0 + wm * 32 + mi * 16 + grp;
            int col = n0 + wn * 16 + ni * 8 + tg * 2;
            C[(size_t)row * Hdim + col]           = acc[mi][ni][0];
            C[(size_t)row * Hdim + col + 1]       = acc[mi][ni][1];
            C[(size_t)(row + 8) * Hdim + col]     = acc[mi][ni][2];
            C[(size_t)(row + 8) * Hdim + col + 1] = acc[mi][ni][3];
        }
    }
}

// ---------------- kernel 3: per-(b,n) dots (register-resident vectors) + epilogue ----------------
__device__ __forceinline__ float wsum(float v) {
    v += __shfl_xor_sync(0xffffffffu, v, 16);
    v += __shfl_xor_sync(0xffffffffu, v, 8);
    v += __shfl_xor_sync(0xffffffffu, v, 4);
    v += __shfl_xor_sync(0xffffffffu, v, 2);
    v += __shfl_xor_sync(0xffffffffu, v, 1);
    return v;
}

__global__ __launch_bounds__(256, 2) void k3_final(const float* __restrict__ sv,
                                                   const int* __restrict__ mask,
                                                   const float* __restrict__ Wc,
                                                   const float* __restrict__ bmat,
                                                   const float* __restrict__ qw,
                                                   const float* __restrict__ qb,
                                                   float* __restrict__ out) {
    const int b    = blockIdx.x;
    const int tid  = threadIdx.x;  // 256
    const int lane = tid & 31;
    const int wid  = tid >> 5;

    __shared__ float sCont[64], sRel[64], sSim[64], sM[64], sQw[64];

    // register-resident vectors: each lane owns idx = lane + 32*i (i<6)
    float4 rc[6], rr[6], rg[6];
    {
        const float4* Wc4 = (const float4*)Wc;
        const float4* Rp  = (const float4*)(g_R + (size_t)b * Hdim);
        const float4* Gp  = (const float4*)(g_G + (size_t)b * Hdim);
#pragma unroll
        for (int i = 0; i < 6; i++) {
            int idx = lane + i * 32;
            rc[i] = Wc4[idx];
            rr[i] = Rp[idx];
            rg[i] = Gp[idx];
        }
    }
    if (tid < 64) {
        sM[tid]  = (tid < Nn && mask[b * Nn + tid] != 0) ? 1.0f : 0.0f;
        sQw[tid] = (tid < Nn) ? qw[tid] : 0.0f;
    }

    for (int n = wid; n < Nn; n += 8) {
        const float4* row = (const float4*)(sv + ((size_t)b * Nn + n) * Hdim);
        float dc = 0.0f, dr = 0.0f, dg = 0.0f;
#pragma unroll
        for (int i = 0; i < 6; i++) {
            float4 v = row[lane + i * 32];
            dc = fmaf(v.x, rc[i].x, dc); dc = fmaf(v.y, rc[i].y, dc);
            dc = fmaf(v.z, rc[i].z, dc); dc = fmaf(v.w, rc[i].w, dc);
            dr = fmaf(v.x, rr[i].x, dr); dr = fmaf(v.y, rr[i].y, dr);
            dr = fmaf(v.z, rr[i].z, dr); dr = fmaf(v.w, rr[i].w, dr);
            dg = fmaf(v.x, rg[i].x, dg); dg = fmaf(v.y, rg[i].y, dg);
            dg = fmaf(v.z, rg[i].z, dg); dg = fmaf(v.w, rg[i].w, dg);
        }
        dc = wsum(dc); dr = wsum(dr); dg = wsum(dg);
        if (lane == 0) { sCont[n] = dc; sRel[n] = dr; sSim[n] = dg; }
    }
    __syncthreads();

    if (wid == 0) {
        const float b00 = bmat[0];
        const float qbv = qb[0];
        const float m1 = sM[lane],       m2 = sM[lane + 32];
        const float q1 = sQw[lane],      q2 = sQw[lane + 32];
        const bool  v2 = (lane + 32) < Nn;

        const float Qm = wsum(m1 * q1 + m2 * q2);        // sum_m q_w[m]*mask[m]
        const float sn = wsum(m1 + m2);                  // sent_num

        // s[n] = q_b + mask[n] * ((rel + cont + b00)*Qm + simdot)
        float s1 = qbv + m1 * ((sRel[lane] + sCont[lane] + b00) * Qm + sSim[lane]);
        float s2 = v2 ? (qbv + m2 * ((sRel[lane + 32] + sCont[lane + 32] + b00) * Qm + sSim[lane + 32]))
                      : 0.0f;

        // layernorm over the 50 sentences
        const float mu = wsum(s1 + (v2 ? s2 : 0.0f)) * (1.0f / (float)Nn);
        const float d1 = s1 - mu;
        const float d2 = v2 ? (s2 - mu) : 0.0f;
        const float var = wsum(d1 * d1 + d2 * d2) * (1.0f / (float)Nn);
        const float rstd = rsqrtf(var + 1e-6f);

        const float sig1 = 1.0f / (1.0f + expf(-d1 * rstd));
        const float sig2 = 1.0f / (1.0f + expf(-d2 * rstd));

        // rank-1 closed form:  M = p * mask^T,  x*sn = (1-l) + l*p[n]*sn
        const float S = wsum(sig1 * m1 + sig2 * m2);
        const float inv = 1.0f / S;
        const float p1 = sig1 * m1 * inv;
        const float p2 = sig2 * m2 * inv;

        float o1 = (1.0f / (1.0f + expf(-(0.2f + 0.8f * p1 * sn)))) * m1;
        out[b * Nn + lane] = o1;
        if (v2) {
            float o2 = (1.0f / (1.0f + expf(-(0.2f + 0.8f * p2 * sn)))) * m2;
            out[b * Nn + lane + 32] = o2;
        }
    }
}

// ---------------- launch ----------------
extern "C" void kernel_launch(void* const* d_in, const int* in_sizes, int n_in,
                              void* d_out, int out_size) {
    const float* sv   = (const float*)d_in[0];
    const int*   mask = (const int*)d_in[1];
    const float* Wc   = (const float*)d_in[2];
    const float* Wsim = (const float*)d_in[3];
    const float* Wrel = (const float*)d_in[4];
    const float* bmat = (const float*)d_in[5];
    const float* qw   = (const float*)d_in[6];
    const float* qb   = (const float*)d_in[7];
    float*       out  = (float*)d_out;

    k1_reduce<<<Bb, 192>>>(sv, mask, qw);
    k2_gemm<<<dim3(Hdim / BN, Bb / BM, 2), 256>>>(Wrel, Wsim);
    k3_final<<<Bb, 256>>>(sv, mask, Wc, bmat, qw, qb, out);
}